// round 13
// baseline (speedup 1.0000x reference)
#include <cuda_runtime.h>
#include <cuda_fp16.h>
#include <math.h>
#include <stdint.h>

#define Bn 256
#define Sn 128
#define ASn 5
#define En 300
#define Hn 300
#define Pn 3
#define Dn 601    // 2*H+1
#define GMK 928   // padded split-K in halves
#define NPs 2432  // padded N (2400 used)
#define LT 256    // lstm threads (8 warps)
#define NSL 15    // j-slices per (dir,bg): 15 x 20 j = 300

// ------------------------- scratch (device globals) -------------------------
__device__ __half g_xh[(size_t)Bn*Sn*GMK];     // A' split embedding [hi|hi|lo]
__device__ __half g_wh[(size_t)NPs*GMK];       // B' split stacked input weights [hi|lo|hi]
__device__ float g_bs[NPs];
__device__ float g_pre[(size_t)Bn*Sn*NPs];
__device__ float g_mem[(size_t)Bn*Sn*Dn];      // locationed memory, written by LSTM directly
__device__ float g_gwihT[Dn*900];
__device__ float g_gwhhT[Hn*900];
__device__ float g_et[Bn*En];
__device__ float g_it[Bn*Dn];
__device__ float g_gi[Bn*900];
__device__ int   g_len[3*Bn];
__device__ int   g_perm[Bn];                   // [group 4][local 64] -> batch row
// LSTM-HMMA structures
__device__ __half g_whh[(size_t)2*NSL*2*80*304];   // [dir][slice][sec][80: 4gates x 20j][304]
__device__ __half g_hsp[(size_t)2*2*4*64*608];     // [parity][dir][bg][b 64][608] (zero-init padding relied on)
__device__ unsigned g_ctrH[8];

__device__ __forceinline__ float sigf(float x){ return 1.f/(1.f+expf(-x)); }

__device__ __forceinline__ uint32_t smem_u32(const void* p){
    uint32_t a;
    asm("{ .reg .u64 t; cvta.to.shared.u64 t, %1; cvt.u32.u64 %0, t; }" : "=r"(a) : "l"(p));
    return a;
}

#define MMA16816(d, a, b0v, b1v) \
    asm volatile("mma.sync.aligned.m16n8k16.row.col.f32.f16.f16.f32 " \
        "{%0,%1,%2,%3}, {%4,%5,%6,%7}, {%8,%9}, {%0,%1,%2,%3};" \
        : "+f"((d)[0]), "+f"((d)[1]), "+f"((d)[2]), "+f"((d)[3]) \
        : "r"((a)[0]), "r"((a)[1]), "r"((a)[2]), "r"((a)[3]), "r"(b0v), "r"(b1v))

#define LDSM_X4(r, addr) \
    asm volatile("ldmatrix.sync.aligned.m8n8.x4.shared.b16 {%0,%1,%2,%3}, [%4];" \
        : "=r"((r)[0]), "=r"((r)[1]), "=r"((r)[2]), "=r"((r)[3]) : "r"(addr))

#define LDSM_X2(r, addr) \
    asm volatile("ldmatrix.sync.aligned.m8n8.x2.shared.b16 {%0,%1}, [%2];" \
        : "=r"((r)[0]), "=r"((r)[1]) : "r"(addr))

// ------------------------- lengths (+ counter reset) -------------------------
__global__ void lengths_kernel(const int* __restrict__ raw,
                               const int* __restrict__ aidx,
                               const int* __restrict__ left)
{
    int b = blockIdx.x;
    int t = threadIdx.x; // 128
    if (b == 0 && t < 8) g_ctrH[t] = 0u;
    int c1 = raw[b*Sn+t]  != 0;
    int c2 = left[b*Sn+t] != 0;
    int c3 = (t < ASn) ? (aidx[b*ASn+t] != 0) : 0;
    int mlen = __syncthreads_count(c1);
    int llen = __syncthreads_count(c2);
    int alen = __syncthreads_count(c3);
    if (t == 0){ g_len[b] = mlen; g_len[Bn+b] = llen; g_len[2*Bn+b] = alen; }
}

// ------------------------- sort batch rows by mem_len desc, deal round-robin ------------
__global__ void sort_kernel()
{
    __shared__ unsigned key[256];
    int t = threadIdx.x;
    key[t] = ((unsigned)g_len[t] << 8) | (unsigned)t;
    __syncthreads();
    for (int k = 2; k <= 256; k <<= 1){
        for (int j = k >> 1; j > 0; j >>= 1){
            int ixj = t ^ j;
            if (ixj > t){
                unsigned a = key[t], b = key[ixj];
                bool up = ((t & k) == 0);
                if (up ? (a < b) : (a > b)){ key[t] = b; key[ixj] = a; }
            }
            __syncthreads();
        }
    }
    g_perm[(t & 3)*64 + (t >> 2)] = (int)(key[t] & 0xFFu);
}

// ------------------------- mega prep: embed + input-w + recur-w + transposes ------------
#define MP_EMB 29696
#define MP_WH  (MP_EMB + 2204)
#define MP_WHH (MP_WH + 1425)
#define MP_TR  (MP_WHH + 1102)

__global__ void megaprep_kernel(const int* __restrict__ raw, const float* __restrict__ emb,
    const float* __restrict__ wf, const float* __restrict__ wb,
    const float* __restrict__ bif, const float* __restrict__ bhf,
    const float* __restrict__ bib, const float* __restrict__ bhb,
    const float* __restrict__ whf, const float* __restrict__ whb,
    const float* __restrict__ gwih, const float* __restrict__ gwhh)
{
    int blk = blockIdx.x;
    int t = threadIdx.x;
    if (blk < MP_EMB){
        int i = blk*256 + t;
        const int F4 = GMK/4;
        int row = i / F4;
        int c4  = i % F4;
        int sec = (c4 < 76) ? 0 : (c4 < 152) ? 1 : (c4 < 228) ? 2 : 3;
        int s4  = c4 - sec*76;
        float4 v = make_float4(0.f,0.f,0.f,0.f);
        if (sec < 3 && s4 < 75){
            int tok = raw[row];
            v = ((const float4*)emb)[(size_t)tok*75 + s4];
        }
        __half o[4];
        float vv[4] = {v.x, v.y, v.z, v.w};
        #pragma unroll
        for (int q = 0; q < 4; q++){
            __half h = __float2half(vv[q]);
            o[q] = (sec == 2) ? __float2half(vv[q] - __half2float(h)) : h;
        }
        *(uint2*)(g_xh + (size_t)row*GMK + c4*4) = *(uint2*)o;
    } else if (blk < MP_WH){
        int i = (blk - MP_EMB)*256 + t;
        const int F4 = GMK/4;
        int n = i / F4;
        int c4 = i % F4;
        int sec = (c4 < 76) ? 0 : (c4 < 152) ? 1 : (c4 < 228) ? 2 : 3;
        int s4  = c4 - sec*76;
        float4 v = make_float4(0.f,0.f,0.f,0.f);
        if (sec < 3 && s4 < 75 && n < 2400){
            const float* wrow = (n < 1200) ? (wf + (size_t)n*300) : (wb + (size_t)(n-1200)*300);
            v = *(const float4*)(wrow + s4*4);
        }
        __half o[4];
        float vv[4] = {v.x, v.y, v.z, v.w};
        #pragma unroll
        for (int q = 0; q < 4; q++){
            __half h = __float2half(vv[q]);
            o[q] = (sec == 1) ? __float2half(vv[q] - __half2float(h)) : h;
        }
        *(uint2*)(g_wh + (size_t)n*GMK + c4*4) = *(uint2*)o;
        if (c4 == 0){
            float b = 0.f;
            if (n < 1200)      b = bif[n] + bhf[n];
            else if (n < 2400) b = bib[n-1200] + bhb[n-1200];
            g_bs[n] = b;
        }
    } else if (blk < MP_WHH){
        // recurrent weight slices: [dir][sl][sec][80][304], row r: gate=r/20, j = sl*20 + r%20
        int idx = (blk - MP_WH)*256 + t;
        int k4 = idx % 76;
        int r  = (idx / 76) % 80;
        int sec = (idx / (76*80)) % 2;
        int sl  = (idx / (76*80*2)) % NSL;
        int dir = idx / (76*80*2*NSL);
        __half o[4];
        if (k4 < 75){
            const float* w = dir ? whb : whf;
            int grow = (r/20)*300 + sl*20 + (r%20);
            float4 v = *(const float4*)(w + (size_t)grow*300 + k4*4);
            float vv[4] = {v.x, v.y, v.z, v.w};
            #pragma unroll
            for (int q = 0; q < 4; q++){
                __half hi = __float2half(vv[q]);
                o[q] = sec ? __float2half(vv[q] - __half2float(hi)) : hi;
            }
        } else {
            o[0]=o[1]=o[2]=o[3]=__float2half(0.f);
        }
        *(uint2*)(g_whh + (size_t)idx*4) = *(uint2*)o;
    } else {
        int lb = blk - MP_WHH;
        int which = lb / 551;
        int rem = lb % 551;
        int c0 = (rem % 19) * 32;
        int r0 = (rem / 19) * 32;
        const float* in = which ? gwhh : gwih;
        float* out = which ? g_gwhhT : g_gwihT;
        int R = 900;
        int C = which ? Hn : Dn;
        __shared__ float tile[32][33];
        int x = t & 31, y = t >> 5;
        #pragma unroll
        for (int i = 0; i < 32; i += 8){
            int r = r0 + y + i, c = c0 + x;
            if (r < R && c < C) tile[y+i][x] = in[(size_t)r*C + c];
        }
        __syncthreads();
        #pragma unroll
        for (int i = 0; i < 32; i += 8){
            int r = r0 + x, c = c0 + y + i;
            if (r < R && c < C) out[(size_t)c*R + r] = tile[x][y+i];
        }
    }
}

// ------------------------- HMMA fp16-split input GEMM (verified R6) ---------------------
#define LROW 40
__global__ void __launch_bounds__(256) gemm_hmma_kernel()
{
    __shared__ __half As[2][128*LROW];
    __shared__ __half Bs[2][128*LROW];

    int t = threadIdx.x;
    int lane = t & 31, wid = t >> 5;
    int wm = wid & 3, wn = wid >> 2;
    int g = lane >> 2, tig = lane & 3;
    int m0 = blockIdx.y * 128;
    int n0 = blockIdx.x * 128;

    int srow = t >> 1;
    int skoff = (t & 1) * 16;
    const __half* Ag = g_xh + (size_t)(m0 + srow)*GMK + skoff;
    const __half* Bg = g_wh + (size_t)(n0 + srow)*GMK + skoff;
    __half* Asm = &As[0][0];
    __half* Bsm = &Bs[0][0];
    int sdst = srow*LROW + skoff;

    const uint32_t asb = smem_u32(&As[0][0]);
    const uint32_t bsb = smem_u32(&Bs[0][0]);
    const uint32_t BUFB = 128*LROW*2;
    int lr15 = lane & 15;
    int lc8  = (lane >> 4) * 8;
    uint32_t aoff[2][2], boff[2][4];
    #pragma unroll
    for (int kt = 0; kt < 2; kt++){
        #pragma unroll
        for (int mt = 0; mt < 2; mt++)
            aoff[kt][mt] = (uint32_t)(((wm*32 + mt*16 + lr15)*LROW + kt*16 + lc8) * 2);
        #pragma unroll
        for (int pr = 0; pr < 4; pr++)
            boff[kt][pr] = (uint32_t)(((wn*64 + pr*16 + lr15)*LROW + kt*16 + lc8) * 2);
    }

    float acc[2][8][4];
    #pragma unroll
    for (int mt = 0; mt < 2; mt++)
        #pragma unroll
        for (int nt = 0; nt < 8; nt++)
            #pragma unroll
            for (int q = 0; q < 4; q++) acc[mt][nt][q] = 0.f;

    const int NC = GMK/32;
    uint4 ra0, ra1, rb0, rb1;

    ra0 = *(const uint4*)(Ag);     ra1 = *(const uint4*)(Ag + 8);
    rb0 = *(const uint4*)(Bg);     rb1 = *(const uint4*)(Bg + 8);
    *(uint4*)(Asm + sdst) = ra0;   *(uint4*)(Asm + sdst + 8) = ra1;
    *(uint4*)(Bsm + sdst) = rb0;   *(uint4*)(Bsm + sdst + 8) = rb1;
    __syncthreads();

    for (int c = 0; c < NC; c++){
        int cur = c & 1;
        if (c + 1 < NC){
            const __half* An = Ag + (c+1)*32;
            const __half* Bq = Bg + (c+1)*32;
            ra0 = *(const uint4*)(An);  ra1 = *(const uint4*)(An + 8);
            rb0 = *(const uint4*)(Bq);  rb1 = *(const uint4*)(Bq + 8);
        }
        uint32_t abuf = asb + cur*BUFB;
        uint32_t bbuf = bsb + cur*BUFB;
        #pragma unroll
        for (int kt = 0; kt < 2; kt++){
            uint32_t af[2][4];
            LDSM_X4(af[0], abuf + aoff[kt][0]);
            LDSM_X4(af[1], abuf + aoff[kt][1]);
            #pragma unroll
            for (int pr = 0; pr < 4; pr++){
                uint32_t bf[4];
                LDSM_X4(bf, bbuf + boff[kt][pr]);
                MMA16816(acc[0][pr*2  ], af[0], bf[0], bf[2]);
                MMA16816(acc[1][pr*2  ], af[1], bf[0], bf[2]);
                MMA16816(acc[0][pr*2+1], af[0], bf[1], bf[3]);
                MMA16816(acc[1][pr*2+1], af[1], bf[1], bf[3]);
            }
        }
        if (c + 1 < NC){
            int nxt = cur ^ 1;
            __half* Ad = &As[nxt][0];
            __half* Bd = &Bs[nxt][0];
            *(uint4*)(Ad + sdst) = ra0;  *(uint4*)(Ad + sdst + 8) = ra1;
            *(uint4*)(Bd + sdst) = rb0;  *(uint4*)(Bd + sdst + 8) = rb1;
        }
        __syncthreads();
    }

    #pragma unroll
    for (int nt = 0; nt < 8; nt++){
        int ncol = n0 + wn*64 + nt*8 + tig*2;
        float b0 = g_bs[ncol], b1 = g_bs[ncol + 1];
        #pragma unroll
        for (int mt = 0; mt < 2; mt++){
            size_t mrow = (size_t)(m0 + wm*32 + mt*16 + g);
            float* p0 = g_pre + mrow*NPs + ncol;
            float2 v0 = make_float2(acc[mt][nt][0] + b0, acc[mt][nt][1] + b1);
            float2 v1 = make_float2(acc[mt][nt][2] + b0, acc[mt][nt][3] + b1);
            *(float2*)p0 = v0;
            *(float2*)(p0 + 8*NPs) = v1;
        }
    }
}

// ------------------------- HMMA BiLSTM: j-sliced, ONE barrier per step -------------------
// 120 blocks = dir(2) x bg(4, 64 sorted batch) x jslice(15, 20 j -> 80 gate rows), 8 warps.
// Each block computes i,f,g,o for its j-chunk -> c/h update is block-local (smem), only the
// h exchange crosses blocks (one fence+barrier per step).
__global__ void __launch_bounds__(LT,1) lstm_hmma_kernel()
{
    extern __shared__ char smx[];
    __half* wsm  = (__half*)smx;                       // [2][80][312]   99840 B
    __half* hsm  = (__half*)(smx + 99840);             // [64][616]      78848 B
    float*  psm  = (float*)(smx + 178688);             // [64][80]       20480 B (pre -> act in place)
    float*  c_s  = (float*)(smx + 199168);             // [64][20]        5120 B
    int*    len_s = (int*)(smx + 204288);              // [64]
    int*    ll_s  = len_s + 64;
    int*    al_s  = ll_s + 64;
    int*    bmap  = al_s + 64;                         // -> 205312 B total

    int t = threadIdx.x, lane = t & 31, wid = t >> 5;
    int bid = blockIdx.x;          // 0..119
    int dir = bid / 60;
    int rem = bid % 60;
    int bg  = rem / NSL;
    int sl  = rem % NSL;
    int grp = dir*4 + bg;          // 0..7
    int j0  = sl*20;

    {
        const __half* wg = g_whh + (size_t)(dir*NSL + sl)*2*80*304;
        for (int i = t; i < 160*38; i += LT){
            int r = i/38, c = i%38;
            *(uint4*)(wsm + r*312 + c*8) = *(const uint4*)(wg + (size_t)r*304 + c*8);
        }
    }
    for (int i = t; i < 64*77; i += LT) *(uint4*)(hsm + i*8) = make_uint4(0,0,0,0);
    for (int i = t; i < 64*20; i += LT) c_s[i] = 0.f;
    if (t < 64){
        int bact = g_perm[bg*64 + t];
        bmap[t]  = bact;
        len_s[t] = g_len[bact];
        ll_s[t]  = g_len[Bn + bact];
        al_s[t]  = g_len[2*Bn + bact];
    }
    __syncthreads();

    int maxlen = len_s[0];   // sorted desc within group

    int wm = wid >> 1, wn = wid & 1;
    int lr15 = lane & 15, lc8 = (lane >> 4)*8;
    int g8 = lane >> 2, tig = lane & 3;
    uint32_t hsb = smem_u32(hsm), wsb = smem_u32(wsm);
    uint32_t arow  = (uint32_t)((wm*16 + lr15)*616 + lc8);
    uint32_t brow0 = (uint32_t)((wn*40 + lr15)*312 + lc8);
    uint32_t brow1 = (uint32_t)((wn*40 + 16 + lr15)*312 + lc8);
    uint32_t brow2 = (uint32_t)((wn*40 + 32 + (lane & 7))*312 + ((lane >> 3) & 1)*8);

    const float* preB = g_pre + dir*1200;
    int nact = 64;

    for (int step = 0; step < maxlen; step++){
        while (nact > 0 && len_s[nact-1] <= step) nact--;

        // ---- prefetch pre for active rows: 4 gate-chunks of 20 floats each ----
        for (int i = t; i < nact*20; i += LT){
            int bl = i/20, r2 = i%20;
            int g = r2/5, q4 = r2%5;
            int L = len_s[bl];
            int pos = dir ? (L-1-step) : step;
            float4 v = *(const float4*)(preB + (size_t)(bmap[bl]*Sn + pos)*NPs + g*300 + j0 + q4*4);
            *(float4*)&psm[bl*80 + g*20 + q4*4] = v;
        }

        // ---- gate MMA (skip fully-frozen m16 tiles) ----
        float acc[5][4];
        #pragma unroll
        for (int n = 0; n < 5; n++)
            #pragma unroll
            for (int q = 0; q < 4; q++) acc[n][q] = 0.f;

        if (wm*16 < nact){
            #pragma unroll 1
            for (int sec = 0; sec < 3; sec++){
                uint32_t acol = (sec == 2) ? 304u : 0u;
                uint32_t wb = wsb + ((sec == 1) ? (uint32_t)(80*312*2) : 0u);
                #pragma unroll 2
                for (int kk = 0; kk < 19; kk++){
                    uint32_t ka = (uint32_t)(kk*16);
                    uint32_t af[4], b0f[4], b1f[4], b2f[2];
                    LDSM_X4(af,  hsb + (arow + acol + ka)*2);
                    LDSM_X4(b0f, wb + (brow0 + ka)*2);
                    LDSM_X4(b1f, wb + (brow1 + ka)*2);
                    LDSM_X2(b2f, wb + (brow2 + ka)*2);
                    MMA16816(acc[0], af, b0f[0], b0f[2]);
                    MMA16816(acc[1], af, b0f[1], b0f[3]);
                    MMA16816(acc[2], af, b1f[0], b1f[2]);
                    MMA16816(acc[3], af, b1f[1], b1f[3]);
                    MMA16816(acc[4], af, b2f[0], b2f[1]);
                }
            }
        }
        __syncthreads();   // psm (pre) ready

        // ---- activations in place: psm[bl][rl] = act(acc + pre) ----
        #pragma unroll
        for (int nt = 0; nt < 5; nt++){
            #pragma unroll
            for (int q = 0; q < 4; q++){
                int rl = wn*40 + nt*8 + tig*2 + (q & 1);
                int bl = wm*16 + g8 + ((q >> 1) << 3);
                if (bl < nact){
                    float x = acc[nt][q] + psm[bl*80 + rl];
                    psm[bl*80 + rl] = (rl >= 40 && rl < 60) ? tanhf(x) : sigf(x);
                }
            }
        }
        __syncthreads();   // activations ready

        // ---- block-local c/h update + fused locmem + hsp write ----
        __half* hw = g_hsp + (size_t)((((step & 1)*2 + dir)*4 + bg))*64*608;
        for (int i = t; i < nact*20; i += LT){
            int bl = i/20, jj = i%20;
            float gi = psm[bl*80 + jj];
            float gf = psm[bl*80 + 20 + jj];
            float gg = psm[bl*80 + 40 + jj];
            float go = psm[bl*80 + 60 + jj];
            float c = gf*c_s[bl*20 + jj] + gi*gg;
            float h = go * tanhf(c);
            c_s[bl*20 + jj] = c;
            int L = len_s[bl];
            int s = dir ? (L-1-step) : step;
            int a_s = ll_s[bl], a_e = a_s + al_s[bl];
            float l;
            if (s < a_s)      l = (float)(a_s - s);
            else if (s < a_e) l = 0.f;
            else              l = (float)(s - a_e + 1);
            float w = 1.f - l/(float)L;
            g_mem[((size_t)bmap[bl]*Sn + s)*Dn + dir*300 + j0 + jj] = h * w;
            __half hi = __float2half(h);
            __half lo = __float2half(h - __half2float(hi));
            hw[bl*608 + j0 + jj] = hi;
            hw[bl*608 + 304 + j0 + jj] = lo;
        }
        // frozen rows: zero g_mem at position `step`
        for (int i = t; i < (64 - nact)*20; i += LT){
            int bl = nact + i/20, jj = i%20;
            g_mem[((size_t)bmap[bl]*Sn + step)*Dn + dir*300 + j0 + jj] = 0.f;
        }
        // u column (one block per group)
        if (dir == 0 && sl == 0 && t < 64){
            int L = len_s[t];
            float u = 0.f;
            int s = step;
            if (step < L){
                int a_s = ll_s[t], a_e = a_s + al_s[t];
                if (s < a_s)      u = (float)(s - a_s);
                else if (s < a_e) u = 0.f;
                else              u = (float)(s - a_e + 1);
            }
            g_mem[((size_t)bmap[t]*Sn + s)*Dn + 600] = u;
        }
        __threadfence();
        __syncthreads();
        if (t == 0){
            unsigned tgt = (unsigned)NSL*(unsigned)(step+1);
            unsigned v = atomicAdd(&g_ctrH[grp], 1u) + 1u;
            while (v < tgt){ __nanosleep(64); v = atomicAdd(&g_ctrH[grp], 0u); }
        }
        __syncthreads();

        // ---- reload h_split for rows active at step+1 ----
        {
            int nc = nact;
            while (nc > 0 && len_s[nc-1] <= step+1) nc--;
            const __half* hr = g_hsp + (size_t)((((step & 1)*2 + dir)*4 + bg))*64*608;
            for (int i = t; i < nc*76; i += LT){
                int r = i/76, c = i%76;
                uint4 v = __ldcg((const uint4*)(hr + (size_t)r*608 + c*8));
                *(uint4*)(hsm + r*616 + c*8) = v;
            }
        }
        __syncthreads();
    }

    // tail: zero g_mem for steps >= maxlen (all 64 rows, this block's j-chunk)
    for (int step = maxlen; step < Sn; step++){
        for (int i = t; i < 64*20; i += LT){
            int bl = i/20, jj = i%20;
            g_mem[((size_t)bmap[bl]*Sn + step)*Dn + dir*300 + j0 + jj] = 0.f;
        }
        if (dir == 0 && sl == 0 && t < 64)
            g_mem[((size_t)bmap[t]*Sn + step)*Dn + 600] = 0.f;
    }
}

// ------------------------- attention (ONCE — alpha/i_t are hop-invariant) ----------------
__global__ void att_kernel(const float* __restrict__ att_w)
{
    int b = blockIdx.x;
    int t = threadIdx.x; // 256
    __shared__ float red[256];
    __shared__ float alpha[Sn];

    for (int d = t; d < En; d += 256) g_et[b*En + d] = 0.f;

    int warp = t >> 5, lane = t & 31;
    for (int s = warp; s < Sn; s += 8){
        const float* mrow = g_mem + ((size_t)b*Sn + s)*Dn;
        float acc = 0.f;
        for (int d = lane; d < Dn; d += 32) acc += mrow[d]*att_w[d];
        #pragma unroll
        for (int o = 16; o > 0; o >>= 1) acc += __shfl_down_sync(0xffffffffu, acc, o);
        if (lane == 0) alpha[s] = acc;
    }
    __syncthreads();

    red[t] = (t < Sn) ? alpha[t] : -1e30f;
    __syncthreads();
    for (int s = 128; s > 0; s >>= 1){ if (t < s) red[t] = fmaxf(red[t], red[t+s]); __syncthreads(); }
    float mx = red[0]; __syncthreads();
    float e = 0.f;
    if (t < Sn){ e = expf(alpha[t] - mx); alpha[t] = e; }
    red[t] = e; __syncthreads();
    for (int s = 128; s > 0; s >>= 1){ if (t < s) red[t] += red[t+s]; __syncthreads(); }
    float inv = 1.f / red[0]; __syncthreads();
    if (t < Sn) alpha[t] *= inv;
    __syncthreads();

    for (int d = t; d < Dn; d += 256){
        float acc = 0.f;
        const float* mp = g_mem + (size_t)b*Sn*Dn + d;
        #pragma unroll 4
        for (int s = 0; s < Sn; s++) acc += alpha[s]*mp[(size_t)s*Dn];
        g_it[b*Dn + d] = acc;
    }
}

// ------------------------- gi = i_t @ gru_w_ih^T + b_ih (ONCE) -------------------------
__global__ void gi_kernel(const float* __restrict__ b_ih)
{
    int b0 = blockIdx.x * 4;
    int t = threadIdx.x; // 320
    __shared__ float it_s[4][604];
    for (int i = t; i < 4*Dn; i += 320){ int r = i/Dn, d = i%Dn; it_s[r][d] = g_it[(b0+r)*Dn + d]; }
    __syncthreads();
    if (t < 300){
        int j = t;
        float gi0[4], gi1[4], gi2[4];
        float bi0 = b_ih[j], bi1 = b_ih[300+j], bi2 = b_ih[600+j];
        #pragma unroll
        for (int r = 0; r < 4; r++){ gi0[r]=bi0; gi1[r]=bi1; gi2[r]=bi2; }
        const float* wp = g_gwihT + j;
        #pragma unroll 2
        for (int d = 0; d < Dn; d++){
            float w0 = wp[(size_t)d*900];
            float w1 = wp[(size_t)d*900 + 300];
            float w2 = wp[(size_t)d*900 + 600];
            #pragma unroll
            for (int r = 0; r < 4; r++){
                float x = it_s[r][d];
                gi0[r] += w0*x; gi1[r] += w1*x; gi2[r] += w2*x;
            }
        }
        #pragma unroll
        for (int r = 0; r < 4; r++){
            g_gi[(b0+r)*900 + j]       = gi0[r];
            g_gi[(b0+r)*900 + 300 + j] = gi1[r];
            g_gi[(b0+r)*900 + 600 + j] = gi2[r];
        }
    }
}

// ------------------------- GRU hop: et update (gh only) -------------------------
__global__ void hop_kernel(const float* __restrict__ b_hh)
{
    int b0 = blockIdx.x * 4;
    int t = threadIdx.x; // 320
    __shared__ float et_s[4][304];
    for (int i = t; i < 4*En; i += 320){ int r = i/En, d = i%En; et_s[r][d] = g_et[(b0+r)*En + d]; }
    __syncthreads();
    if (t < 300){
        int j = t;
        float gh0[4], gh1[4], gh2[4];
        float bh0 = b_hh[j], bh1 = b_hh[300+j], bh2 = b_hh[600+j];
        #pragma unroll
        for (int r = 0; r < 4; r++){ gh0[r]=bh0; gh1[r]=bh1; gh2[r]=bh2; }
        const float* hp = g_gwhhT + j;
        #pragma unroll 2
        for (int d = 0; d < En; d++){
            float w0 = hp[(size_t)d*900];
            float w1 = hp[(size_t)d*900 + 300];
            float w2 = hp[(size_t)d*900 + 600];
            #pragma unroll
            for (int r = 0; r < 4; r++){
                float x = et_s[r][d];
                gh0[r] += w0*x; gh1[r] += w1*x; gh2[r] += w2*x;
            }
        }
        #pragma unroll
        for (int r = 0; r < 4; r++){
            float gi0 = g_gi[(b0+r)*900 + j];
            float gi1 = g_gi[(b0+r)*900 + 300 + j];
            float gi2 = g_gi[(b0+r)*900 + 600 + j];
            float rr = sigf(gi0 + gh0[r]);
            float z  = sigf(gi1 + gh1[r]);
            float n  = tanhf(gi2 + rr*gh2[r]);
            g_et[(b0+r)*En + j] = (1.f - z)*n + z*et_s[r][j];
        }
    }
}

// ------------------------- dense head -------------------------
__global__ void dense_kernel(const float* __restrict__ dw, const float* __restrict__ db,
                             float* __restrict__ out)
{
    int b = blockIdx.x;
    int t = threadIdx.x; // 96
    int p = t >> 5, lane = t & 31;
    float acc = 0.f;
    for (int d = lane; d < En; d += 32) acc += g_et[b*En + d]*dw[p*En + d];
    #pragma unroll
    for (int o = 16; o > 0; o >>= 1) acc += __shfl_down_sync(0xffffffffu, acc, o);
    if (lane == 0) out[b*Pn + p] = acc + db[p];
}

// ------------------------- launch -------------------------
extern "C" void kernel_launch(void* const* d_in, const int* in_sizes, int n_in,
                              void* d_out, int out_size)
{
    const int*   raw    = (const int*)d_in[0];
    const int*   aidx   = (const int*)d_in[1];
    const int*   left   = (const int*)d_in[2];
    const float* emb    = (const float*)d_in[3];
    const float* w_ih_f = (const float*)d_in[4];
    const float* w_hh_f = (const float*)d_in[5];
    const float* b_ih_f = (const float*)d_in[6];
    const float* b_hh_f = (const float*)d_in[7];
    const float* w_ih_b = (const float*)d_in[8];
    const float* w_hh_b = (const float*)d_in[9];
    const float* b_ih_b = (const float*)d_in[10];
    const float* b_hh_b = (const float*)d_in[11];
    const float* att_w  = (const float*)d_in[12];
    const float* gw_ih  = (const float*)d_in[14];
    const float* gw_hh  = (const float*)d_in[15];
    const float* gb_ih  = (const float*)d_in[16];
    const float* gb_hh  = (const float*)d_in[17];
    const float* dw     = (const float*)d_in[18];
    const float* db     = (const float*)d_in[19];
    float* out = (float*)d_out;

    const int LSTM_SMEM = 205312;
    cudaFuncSetAttribute(lstm_hmma_kernel,
                         cudaFuncAttributeMaxDynamicSharedMemorySize, LSTM_SMEM);

    lengths_kernel<<<Bn, Sn>>>(raw, aidx, left);                              // 0
    sort_kernel<<<1, 256>>>();                                                // 1
    megaprep_kernel<<<MP_TR, 256>>>(raw, emb, w_ih_f, w_ih_b,
                                    b_ih_f, b_hh_f, b_ih_b, b_hh_b,
                                    w_hh_f, w_hh_b, gw_ih, gw_hh);            // 2
    gemm_hmma_kernel<<<dim3(NPs/128, (Bn*Sn)/128), 256>>>();                  // 3
    lstm_hmma_kernel<<<120, LT, LSTM_SMEM>>>();                               // 4

    att_kernel<<<Bn, 256>>>(att_w);
    gi_kernel<<<64, 320>>>(gb_ih);
    for (int hop = 0; hop < 3; hop++)
        hop_kernel<<<64, 320>>>(gb_hh);
    dense_kernel<<<Bn, 96>>>(dw, db, out);
}

// round 14
// speedup vs baseline: 1.4154x; 1.4154x over previous
#include <cuda_runtime.h>
#include <cuda_fp16.h>
#include <math.h>
#include <stdint.h>

#define Bn 256
#define Sn 128
#define ASn 5
#define En 300
#define Hn 300
#define Pn 3
#define Dn 601    // 2*H+1
#define GMK 928   // padded split-K in halves
#define NPs 2432  // padded N (2400 used)
#define LT 256    // lstm threads (8 warps)
#define NSL 15    // j-slices per (dir,bg): 15 x 20 j = 300

// ------------------------- scratch (device globals) -------------------------
__device__ __half g_xh[(size_t)Bn*Sn*GMK];     // A' split embedding [hi|hi|lo]
__device__ __half g_wh[(size_t)NPs*GMK];       // B' split stacked input weights [hi|lo|hi]
__device__ float g_bs[NPs];
__device__ float g_pre[(size_t)Bn*Sn*NPs];
__device__ float g_mem[(size_t)Bn*Sn*Dn];      // locationed memory, written by LSTM directly
__device__ float g_gwihT[Dn*900];
__device__ float g_gwhhT[Hn*900];
__device__ float g_et[Bn*En];
__device__ float g_it[Bn*Dn];
__device__ float g_gi[Bn*900];
__device__ int   g_len[3*Bn];
__device__ int   g_perm[Bn];                   // [group 4][local 64] -> batch row
// LSTM-HMMA structures
__device__ __half g_whh[(size_t)2*NSL*2*80*304];   // [dir][slice][sec][80: 4gates x 20j][304]
__device__ __half g_hsp[(size_t)2*2*4*64*608];     // [parity][dir][bg][b 64][608] (zero-init padding relied on)
__device__ unsigned g_ctrH[8];

__device__ __forceinline__ float sigf(float x){ return 1.f/(1.f+expf(-x)); }

__device__ __forceinline__ uint32_t smem_u32(const void* p){
    uint32_t a;
    asm("{ .reg .u64 t; cvta.to.shared.u64 t, %1; cvt.u32.u64 %0, t; }" : "=r"(a) : "l"(p));
    return a;
}

#define MMA16816(d, a, b0v, b1v) \
    asm volatile("mma.sync.aligned.m16n8k16.row.col.f32.f16.f16.f32 " \
        "{%0,%1,%2,%3}, {%4,%5,%6,%7}, {%8,%9}, {%0,%1,%2,%3};" \
        : "+f"((d)[0]), "+f"((d)[1]), "+f"((d)[2]), "+f"((d)[3]) \
        : "r"((a)[0]), "r"((a)[1]), "r"((a)[2]), "r"((a)[3]), "r"(b0v), "r"(b1v))

#define LDSM_X4(r, addr) \
    asm volatile("ldmatrix.sync.aligned.m8n8.x4.shared.b16 {%0,%1,%2,%3}, [%4];" \
        : "=r"((r)[0]), "=r"((r)[1]), "=r"((r)[2]), "=r"((r)[3]) : "r"(addr))

#define LDSM_X2(r, addr) \
    asm volatile("ldmatrix.sync.aligned.m8n8.x2.shared.b16 {%0,%1}, [%2];" \
        : "=r"((r)[0]), "=r"((r)[1]) : "r"(addr))

// ------------------------- lengths (+ counter reset) -------------------------
__global__ void lengths_kernel(const int* __restrict__ raw,
                               const int* __restrict__ aidx,
                               const int* __restrict__ left)
{
    int b = blockIdx.x;
    int t = threadIdx.x; // 128
    if (b == 0 && t < 8) g_ctrH[t] = 0u;
    int c1 = raw[b*Sn+t]  != 0;
    int c2 = left[b*Sn+t] != 0;
    int c3 = (t < ASn) ? (aidx[b*ASn+t] != 0) : 0;
    int mlen = __syncthreads_count(c1);
    int llen = __syncthreads_count(c2);
    int alen = __syncthreads_count(c3);
    if (t == 0){ g_len[b] = mlen; g_len[Bn+b] = llen; g_len[2*Bn+b] = alen; }
}

// ------------------------- sort batch rows by mem_len desc, deal round-robin ------------
__global__ void sort_kernel()
{
    __shared__ unsigned key[256];
    int t = threadIdx.x;
    key[t] = ((unsigned)g_len[t] << 8) | (unsigned)t;
    __syncthreads();
    for (int k = 2; k <= 256; k <<= 1){
        for (int j = k >> 1; j > 0; j >>= 1){
            int ixj = t ^ j;
            if (ixj > t){
                unsigned a = key[t], b = key[ixj];
                bool up = ((t & k) == 0);
                if (up ? (a < b) : (a > b)){ key[t] = b; key[ixj] = a; }
            }
            __syncthreads();
        }
    }
    g_perm[(t & 3)*64 + (t >> 2)] = (int)(key[t] & 0xFFu);
}

// ------------------------- mega prep: embed + input-w + recur-w + transposes ------------
#define MP_EMB 29696
#define MP_WH  (MP_EMB + 2204)
#define MP_WHH (MP_WH + 1425)
#define MP_TR  (MP_WHH + 1102)

__global__ void megaprep_kernel(const int* __restrict__ raw, const float* __restrict__ emb,
    const float* __restrict__ wf, const float* __restrict__ wb,
    const float* __restrict__ bif, const float* __restrict__ bhf,
    const float* __restrict__ bib, const float* __restrict__ bhb,
    const float* __restrict__ whf, const float* __restrict__ whb,
    const float* __restrict__ gwih, const float* __restrict__ gwhh)
{
    int blk = blockIdx.x;
    int t = threadIdx.x;
    if (blk < MP_EMB){
        int i = blk*256 + t;
        const int F4 = GMK/4;
        int row = i / F4;
        int c4  = i % F4;
        int sec = (c4 < 76) ? 0 : (c4 < 152) ? 1 : (c4 < 228) ? 2 : 3;
        int s4  = c4 - sec*76;
        float4 v = make_float4(0.f,0.f,0.f,0.f);
        if (sec < 3 && s4 < 75){
            int tok = raw[row];
            v = ((const float4*)emb)[(size_t)tok*75 + s4];
        }
        __half o[4];
        float vv[4] = {v.x, v.y, v.z, v.w};
        #pragma unroll
        for (int q = 0; q < 4; q++){
            __half h = __float2half(vv[q]);
            o[q] = (sec == 2) ? __float2half(vv[q] - __half2float(h)) : h;
        }
        *(uint2*)(g_xh + (size_t)row*GMK + c4*4) = *(uint2*)o;
    } else if (blk < MP_WH){
        int i = (blk - MP_EMB)*256 + t;
        const int F4 = GMK/4;
        int n = i / F4;
        int c4 = i % F4;
        int sec = (c4 < 76) ? 0 : (c4 < 152) ? 1 : (c4 < 228) ? 2 : 3;
        int s4  = c4 - sec*76;
        float4 v = make_float4(0.f,0.f,0.f,0.f);
        if (sec < 3 && s4 < 75 && n < 2400){
            const float* wrow = (n < 1200) ? (wf + (size_t)n*300) : (wb + (size_t)(n-1200)*300);
            v = *(const float4*)(wrow + s4*4);
        }
        __half o[4];
        float vv[4] = {v.x, v.y, v.z, v.w};
        #pragma unroll
        for (int q = 0; q < 4; q++){
            __half h = __float2half(vv[q]);
            o[q] = (sec == 1) ? __float2half(vv[q] - __half2float(h)) : h;
        }
        *(uint2*)(g_wh + (size_t)n*GMK + c4*4) = *(uint2*)o;
        if (c4 == 0){
            float b = 0.f;
            if (n < 1200)      b = bif[n] + bhf[n];
            else if (n < 2400) b = bib[n-1200] + bhb[n-1200];
            g_bs[n] = b;
        }
    } else if (blk < MP_WHH){
        // recurrent weight slices: [dir][sl][sec][80][304], row r: gate=r/20, j = sl*20 + r%20
        int idx = (blk - MP_WH)*256 + t;
        int k4 = idx % 76;
        int r  = (idx / 76) % 80;
        int sec = (idx / (76*80)) % 2;
        int sl  = (idx / (76*80*2)) % NSL;
        int dir = idx / (76*80*2*NSL);
        __half o[4];
        if (k4 < 75){
            const float* w = dir ? whb : whf;
            int grow = (r/20)*300 + sl*20 + (r%20);
            float4 v = *(const float4*)(w + (size_t)grow*300 + k4*4);
            float vv[4] = {v.x, v.y, v.z, v.w};
            #pragma unroll
            for (int q = 0; q < 4; q++){
                __half hi = __float2half(vv[q]);
                o[q] = sec ? __float2half(vv[q] - __half2float(hi)) : hi;
            }
        } else {
            o[0]=o[1]=o[2]=o[3]=__float2half(0.f);
        }
        *(uint2*)(g_whh + (size_t)idx*4) = *(uint2*)o;
    } else {
        int lb = blk - MP_WHH;
        int which = lb / 551;
        int rem = lb % 551;
        int c0 = (rem % 19) * 32;
        int r0 = (rem / 19) * 32;
        const float* in = which ? gwhh : gwih;
        float* out = which ? g_gwhhT : g_gwihT;
        int R = 900;
        int C = which ? Hn : Dn;
        __shared__ float tile[32][33];
        int x = t & 31, y = t >> 5;
        #pragma unroll
        for (int i = 0; i < 32; i += 8){
            int r = r0 + y + i, c = c0 + x;
            if (r < R && c < C) tile[y+i][x] = in[(size_t)r*C + c];
        }
        __syncthreads();
        #pragma unroll
        for (int i = 0; i < 32; i += 8){
            int r = r0 + x, c = c0 + y + i;
            if (r < R && c < C) out[(size_t)c*R + r] = tile[x][y+i];
        }
    }
}

// ------------------------- HMMA fp16-split input GEMM (verified R6) ---------------------
#define LROW 40
__global__ void __launch_bounds__(256) gemm_hmma_kernel()
{
    __shared__ __half As[2][128*LROW];
    __shared__ __half Bs[2][128*LROW];

    int t = threadIdx.x;
    int lane = t & 31, wid = t >> 5;
    int wm = wid & 3, wn = wid >> 2;
    int g = lane >> 2, tig = lane & 3;
    int m0 = blockIdx.y * 128;
    int n0 = blockIdx.x * 128;

    int srow = t >> 1;
    int skoff = (t & 1) * 16;
    const __half* Ag = g_xh + (size_t)(m0 + srow)*GMK + skoff;
    const __half* Bg = g_wh + (size_t)(n0 + srow)*GMK + skoff;
    __half* Asm = &As[0][0];
    __half* Bsm = &Bs[0][0];
    int sdst = srow*LROW + skoff;

    const uint32_t asb = smem_u32(&As[0][0]);
    const uint32_t bsb = smem_u32(&Bs[0][0]);
    const uint32_t BUFB = 128*LROW*2;
    int lr15 = lane & 15;
    int lc8  = (lane >> 4) * 8;
    uint32_t aoff[2][2], boff[2][4];
    #pragma unroll
    for (int kt = 0; kt < 2; kt++){
        #pragma unroll
        for (int mt = 0; mt < 2; mt++)
            aoff[kt][mt] = (uint32_t)(((wm*32 + mt*16 + lr15)*LROW + kt*16 + lc8) * 2);
        #pragma unroll
        for (int pr = 0; pr < 4; pr++)
            boff[kt][pr] = (uint32_t)(((wn*64 + pr*16 + lr15)*LROW + kt*16 + lc8) * 2);
    }

    float acc[2][8][4];
    #pragma unroll
    for (int mt = 0; mt < 2; mt++)
        #pragma unroll
        for (int nt = 0; nt < 8; nt++)
            #pragma unroll
            for (int q = 0; q < 4; q++) acc[mt][nt][q] = 0.f;

    const int NC = GMK/32;
    uint4 ra0, ra1, rb0, rb1;

    ra0 = *(const uint4*)(Ag);     ra1 = *(const uint4*)(Ag + 8);
    rb0 = *(const uint4*)(Bg);     rb1 = *(const uint4*)(Bg + 8);
    *(uint4*)(Asm + sdst) = ra0;   *(uint4*)(Asm + sdst + 8) = ra1;
    *(uint4*)(Bsm + sdst) = rb0;   *(uint4*)(Bsm + sdst + 8) = rb1;
    __syncthreads();

    for (int c = 0; c < NC; c++){
        int cur = c & 1;
        if (c + 1 < NC){
            const __half* An = Ag + (c+1)*32;
            const __half* Bq = Bg + (c+1)*32;
            ra0 = *(const uint4*)(An);  ra1 = *(const uint4*)(An + 8);
            rb0 = *(const uint4*)(Bq);  rb1 = *(const uint4*)(Bq + 8);
        }
        uint32_t abuf = asb + cur*BUFB;
        uint32_t bbuf = bsb + cur*BUFB;
        #pragma unroll
        for (int kt = 0; kt < 2; kt++){
            uint32_t af[2][4];
            LDSM_X4(af[0], abuf + aoff[kt][0]);
            LDSM_X4(af[1], abuf + aoff[kt][1]);
            #pragma unroll
            for (int pr = 0; pr < 4; pr++){
                uint32_t bf[4];
                LDSM_X4(bf, bbuf + boff[kt][pr]);
                MMA16816(acc[0][pr*2  ], af[0], bf[0], bf[2]);
                MMA16816(acc[1][pr*2  ], af[1], bf[0], bf[2]);
                MMA16816(acc[0][pr*2+1], af[0], bf[1], bf[3]);
                MMA16816(acc[1][pr*2+1], af[1], bf[1], bf[3]);
            }
        }
        if (c + 1 < NC){
            int nxt = cur ^ 1;
            __half* Ad = &As[nxt][0];
            __half* Bd = &Bs[nxt][0];
            *(uint4*)(Ad + sdst) = ra0;  *(uint4*)(Ad + sdst + 8) = ra1;
            *(uint4*)(Bd + sdst) = rb0;  *(uint4*)(Bd + sdst + 8) = rb1;
        }
        __syncthreads();
    }

    #pragma unroll
    for (int nt = 0; nt < 8; nt++){
        int ncol = n0 + wn*64 + nt*8 + tig*2;
        float b0 = g_bs[ncol], b1 = g_bs[ncol + 1];
        #pragma unroll
        for (int mt = 0; mt < 2; mt++){
            size_t mrow = (size_t)(m0 + wm*32 + mt*16 + g);
            float* p0 = g_pre + mrow*NPs + ncol;
            float2 v0 = make_float2(acc[mt][nt][0] + b0, acc[mt][nt][1] + b1);
            float2 v1 = make_float2(acc[mt][nt][2] + b0, acc[mt][nt][3] + b1);
            *(float2*)p0 = v0;
            *(float2*)(p0 + 8*NPs) = v1;
        }
    }
}

// ------------------------- HMMA BiLSTM: j-sliced, ONE barrier per step -------------------
// 120 blocks = dir(2) x bg(4, 64 sorted batch) x jslice(15, 20 j -> 80 gate rows), 8 warps.
__global__ void __launch_bounds__(LT,1) lstm_hmma_kernel()
{
    extern __shared__ char smx[];
    __half* wsm  = (__half*)smx;                       // [2][80][312]   99840 B
    __half* hsm  = (__half*)(smx + 99840);             // [64][616]      78848 B
    float*  psm  = (float*)(smx + 178688);             // [64][80]       20480 B (pre -> act in place)
    float*  c_s  = (float*)(smx + 199168);             // [64][20]        5120 B
    int*    len_s = (int*)(smx + 204288);              // [64]
    int*    ll_s  = len_s + 64;
    int*    al_s  = ll_s + 64;
    int*    bmap  = al_s + 64;                         // -> 205312 B total

    int t = threadIdx.x, lane = t & 31, wid = t >> 5;
    int bid = blockIdx.x;          // 0..119
    int dir = bid / 60;
    int rem = bid % 60;
    int bg  = rem / NSL;
    int sl  = rem % NSL;
    int grp = dir*4 + bg;          // 0..7
    int j0  = sl*20;

    {
        const __half* wg = g_whh + (size_t)(dir*NSL + sl)*2*80*304;
        for (int i = t; i < 160*38; i += LT){
            int r = i/38, c = i%38;
            *(uint4*)(wsm + r*312 + c*8) = *(const uint4*)(wg + (size_t)r*304 + c*8);
        }
    }
    for (int i = t; i < 64*77; i += LT) *(uint4*)(hsm + i*8) = make_uint4(0,0,0,0);
    for (int i = t; i < 64*20; i += LT) c_s[i] = 0.f;
    if (t < 64){
        int bact = g_perm[bg*64 + t];
        bmap[t]  = bact;
        len_s[t] = g_len[bact];
        ll_s[t]  = g_len[Bn + bact];
        al_s[t]  = g_len[2*Bn + bact];
    }
    __syncthreads();

    int maxlen = len_s[0];   // sorted desc within group

    int wm = wid >> 1, wn = wid & 1;
    int lr15 = lane & 15, lc8 = (lane >> 4)*8;
    int g8 = lane >> 2, tig = lane & 3;
    uint32_t hsb = smem_u32(hsm), wsb = smem_u32(wsm);
    uint32_t arow  = (uint32_t)((wm*16 + lr15)*616 + lc8);
    uint32_t brow0 = (uint32_t)((wn*40 + lr15)*312 + lc8);
    uint32_t brow1 = (uint32_t)((wn*40 + 16 + lr15)*312 + lc8);
    uint32_t brow2 = (uint32_t)((wn*40 + 32 + (lane & 7))*312 + ((lane >> 3) & 1)*8);

    const float* preB = g_pre + dir*1200;
    int nact = 64;

    for (int step = 0; step < maxlen; step++){
        while (nact > 0 && len_s[nact-1] <= step) nact--;

        // ---- prefetch pre for active rows: 4 gate-chunks of 20 floats each ----
        for (int i = t; i < nact*20; i += LT){
            int bl = i/20, r2 = i%20;
            int g = r2/5, q4 = r2%5;
            int L = len_s[bl];
            int pos = dir ? (L-1-step) : step;
            float4 v = *(const float4*)(preB + (size_t)(bmap[bl]*Sn + pos)*NPs + g*300 + j0 + q4*4);
            *(float4*)&psm[bl*80 + g*20 + q4*4] = v;
        }

        // ---- gate MMA (skip fully-frozen m16 tiles) ----
        float acc[5][4];
        #pragma unroll
        for (int n = 0; n < 5; n++)
            #pragma unroll
            for (int q = 0; q < 4; q++) acc[n][q] = 0.f;

        if (wm*16 < nact){
            #pragma unroll 1
            for (int sec = 0; sec < 3; sec++){
                uint32_t acol = (sec == 2) ? 304u : 0u;
                uint32_t wb = wsb + ((sec == 1) ? (uint32_t)(80*312*2) : 0u);
                #pragma unroll 2
                for (int kk = 0; kk < 19; kk++){
                    uint32_t ka = (uint32_t)(kk*16);
                    uint32_t af[4], b0f[4], b1f[4], b2f[2];
                    LDSM_X4(af,  hsb + (arow + acol + ka)*2);
                    LDSM_X4(b0f, wb + (brow0 + ka)*2);
                    LDSM_X4(b1f, wb + (brow1 + ka)*2);
                    LDSM_X2(b2f, wb + (brow2 + ka)*2);
                    MMA16816(acc[0], af, b0f[0], b0f[2]);
                    MMA16816(acc[1], af, b0f[1], b0f[3]);
                    MMA16816(acc[2], af, b1f[0], b1f[2]);
                    MMA16816(acc[3], af, b1f[1], b1f[3]);
                    MMA16816(acc[4], af, b2f[0], b2f[1]);
                }
            }
        }
        __syncthreads();   // psm (pre) ready

        // ---- activations in place: psm[bl][rl] = act(acc + pre) ----
        #pragma unroll
        for (int nt = 0; nt < 5; nt++){
            #pragma unroll
            for (int q = 0; q < 4; q++){
                int rl = wn*40 + nt*8 + tig*2 + (q & 1);
                int bl = wm*16 + g8 + ((q >> 1) << 3);
                if (bl < nact){
                    float x = acc[nt][q] + psm[bl*80 + rl];
                    psm[bl*80 + rl] = (rl >= 40 && rl < 60) ? tanhf(x) : sigf(x);
                }
            }
        }
        __syncthreads();   // activations ready

        // ---- block-local c/h update + fused locmem + hsp write ----
        __half* hw = g_hsp + (size_t)((((step & 1)*2 + dir)*4 + bg))*64*608;
        for (int i = t; i < nact*20; i += LT){
            int bl = i/20, jj = i%20;
            float gi = psm[bl*80 + jj];
            float gf = psm[bl*80 + 20 + jj];
            float gg = psm[bl*80 + 40 + jj];
            float go = psm[bl*80 + 60 + jj];
            float c = gf*c_s[bl*20 + jj] + gi*gg;
            float h = go * tanhf(c);
            c_s[bl*20 + jj] = c;
            int L = len_s[bl];
            int s = dir ? (L-1-step) : step;
            int a_s = ll_s[bl], a_e = a_s + al_s[bl];
            float l;
            if (s < a_s)      l = (float)(a_s - s);
            else if (s < a_e) l = 0.f;
            else              l = (float)(s - a_e + 1);
            float w = 1.f - l/(float)L;
            g_mem[((size_t)bmap[bl]*Sn + s)*Dn + dir*300 + j0 + jj] = h * w;
            __half hi = __float2half(h);
            __half lo = __float2half(h - __half2float(hi));
            hw[bl*608 + j0 + jj] = hi;
            hw[bl*608 + 304 + j0 + jj] = lo;
        }
        for (int i = t; i < (64 - nact)*20; i += LT){
            int bl = nact + i/20, jj = i%20;
            g_mem[((size_t)bmap[bl]*Sn + step)*Dn + dir*300 + j0 + jj] = 0.f;
        }
        if (dir == 0 && sl == 0 && t < 64){
            int L = len_s[t];
            float u = 0.f;
            int s = step;
            if (step < L){
                int a_s = ll_s[t], a_e = a_s + al_s[t];
                if (s < a_s)      u = (float)(s - a_s);
                else if (s < a_e) u = 0.f;
                else              u = (float)(s - a_e + 1);
            }
            g_mem[((size_t)bmap[t]*Sn + s)*Dn + 600] = u;
        }
        __threadfence();
        __syncthreads();
        if (t == 0){
            unsigned tgt = (unsigned)NSL*(unsigned)(step+1);
            unsigned v = atomicAdd(&g_ctrH[grp], 1u) + 1u;
            while (v < tgt){ __nanosleep(64); v = atomicAdd(&g_ctrH[grp], 0u); }
        }
        __syncthreads();

        // ---- reload h_split for rows active at step+1 ----
        {
            int nc = nact;
            while (nc > 0 && len_s[nc-1] <= step+1) nc--;
            const __half* hr = g_hsp + (size_t)((((step & 1)*2 + dir)*4 + bg))*64*608;
            for (int i = t; i < nc*76; i += LT){
                int r = i/76, c = i%76;
                uint4 v = __ldcg((const uint4*)(hr + (size_t)r*608 + c*8));
                *(uint4*)(hsm + r*616 + c*8) = v;
            }
        }
        __syncthreads();
    }

    // tail: zero g_mem for steps >= maxlen (all 64 rows, this block's j-chunk)
    for (int step = maxlen; step < Sn; step++){
        for (int i = t; i < 64*20; i += LT){
            int bl = i/20, jj = i%20;
            g_mem[((size_t)bmap[bl]*Sn + step)*Dn + dir*300 + j0 + jj] = 0.f;
        }
        if (dir == 0 && sl == 0 && t < 64)
            g_mem[((size_t)bmap[t]*Sn + step)*Dn + 600] = 0.f;
    }
}

// ------------------------- attention (ONCE — alpha/i_t are hop-invariant) ----------------
__global__ void att_kernel(const float* __restrict__ att_w)
{
    int b = blockIdx.x;
    int t = threadIdx.x; // 256
    __shared__ float red[256];
    __shared__ float alpha[Sn];

    for (int d = t; d < En; d += 256) g_et[b*En + d] = 0.f;

    int warp = t >> 5, lane = t & 31;
    for (int s = warp; s < Sn; s += 8){
        const float* mrow = g_mem + ((size_t)b*Sn + s)*Dn;
        float acc = 0.f;
        for (int d = lane; d < Dn; d += 32) acc += mrow[d]*att_w[d];
        #pragma unroll
        for (int o = 16; o > 0; o >>= 1) acc += __shfl_down_sync(0xffffffffu, acc, o);
        if (lane == 0) alpha[s] = acc;
    }
    __syncthreads();

    red[t] = (t < Sn) ? alpha[t] : -1e30f;
    __syncthreads();
    for (int s = 128; s > 0; s >>= 1){ if (t < s) red[t] = fmaxf(red[t], red[t+s]); __syncthreads(); }
    float mx = red[0]; __syncthreads();
    float e = 0.f;
    if (t < Sn){ e = expf(alpha[t] - mx); alpha[t] = e; }
    red[t] = e; __syncthreads();
    for (int s = 128; s > 0; s >>= 1){ if (t < s) red[t] += red[t+s]; __syncthreads(); }
    float inv = 1.f / red[0]; __syncthreads();
    if (t < Sn) alpha[t] *= inv;
    __syncthreads();

    for (int d = t; d < Dn; d += 256){
        float acc = 0.f;
        const float* mp = g_mem + (size_t)b*Sn*Dn + d;
        #pragma unroll 4
        for (int s = 0; s < Sn; s++) acc += alpha[s]*mp[(size_t)s*Dn];
        g_it[b*Dn + d] = acc;
    }
}

// ------------------------- gi = i_t @ gru_w_ih^T + b_ih (ONCE) -------------------------
__global__ void gi_kernel(const float* __restrict__ b_ih)
{
    int b0 = blockIdx.x * 4;
    int t = threadIdx.x; // 320
    __shared__ float it_s[4][604];
    for (int i = t; i < 4*Dn; i += 320){ int r = i/Dn, d = i%Dn; it_s[r][d] = g_it[(b0+r)*Dn + d]; }
    __syncthreads();
    if (t < 300){
        int j = t;
        float gi0[4], gi1[4], gi2[4];
        float bi0 = b_ih[j], bi1 = b_ih[300+j], bi2 = b_ih[600+j];
        #pragma unroll
        for (int r = 0; r < 4; r++){ gi0[r]=bi0; gi1[r]=bi1; gi2[r]=bi2; }
        const float* wp = g_gwihT + j;
        #pragma unroll 2
        for (int d = 0; d < Dn; d++){
            float w0 = wp[(size_t)d*900];
            float w1 = wp[(size_t)d*900 + 300];
            float w2 = wp[(size_t)d*900 + 600];
            #pragma unroll
            for (int r = 0; r < 4; r++){
                float x = it_s[r][d];
                gi0[r] += w0*x; gi1[r] += w1*x; gi2[r] += w2*x;
            }
        }
        #pragma unroll
        for (int r = 0; r < 4; r++){
            g_gi[(b0+r)*900 + j]       = gi0[r];
            g_gi[(b0+r)*900 + 300 + j] = gi1[r];
            g_gi[(b0+r)*900 + 600 + j] = gi2[r];
        }
    }
}

// ------------------------- GRU hop: et update (gh only) -------------------------
__global__ void hop_kernel(const float* __restrict__ b_hh)
{
    int b0 = blockIdx.x * 4;
    int t = threadIdx.x; // 320
    __shared__ float et_s[4][304];
    for (int i = t; i < 4*En; i += 320){ int r = i/En, d = i%En; et_s[r][d] = g_et[(b0+r)*En + d]; }
    __syncthreads();
    if (t < 300){
        int j = t;
        float gh0[4], gh1[4], gh2[4];
        float bh0 = b_hh[j], bh1 = b_hh[300+j], bh2 = b_hh[600+j];
        #pragma unroll
        for (int r = 0; r < 4; r++){ gh0[r]=bh0; gh1[r]=bh1; gh2[r]=bh2; }
        const float* hp = g_gwhhT + j;
        #pragma unroll 2
        for (int d = 0; d < En; d++){
            float w0 = hp[(size_t)d*900];
            float w1 = hp[(size_t)d*900 + 300];
            float w2 = hp[(size_t)d*900 + 600];
            #pragma unroll
            for (int r = 0; r < 4; r++){
                float x = et_s[r][d];
                gh0[r] += w0*x; gh1[r] += w1*x; gh2[r] += w2*x;
            }
        }
        #pragma unroll
        for (int r = 0; r < 4; r++){
            float gi0 = g_gi[(b0+r)*900 + j];
            float gi1 = g_gi[(b0+r)*900 + 300 + j];
            float gi2 = g_gi[(b0+r)*900 + 600 + j];
            float rr = sigf(gi0 + gh0[r]);
            float z  = sigf(gi1 + gh1[r]);
            float n  = tanhf(gi2 + rr*gh2[r]);
            g_et[(b0+r)*En + j] = (1.f - z)*n + z*et_s[r][j];
        }
    }
}

// ------------------------- dense head -------------------------
__global__ void dense_kernel(const float* __restrict__ dw, const float* __restrict__ db,
                             float* __restrict__ out)
{
    int b = blockIdx.x;
    int t = threadIdx.x; // 96
    int p = t >> 5, lane = t & 31;
    float acc = 0.f;
    for (int d = lane; d < En; d += 32) acc += g_et[b*En + d]*dw[p*En + d];
    #pragma unroll
    for (int o = 16; o > 0; o >>= 1) acc += __shfl_down_sync(0xffffffffu, acc, o);
    if (lane == 0) out[b*Pn + p] = acc + db[p];
}

// ------------------------- launch -------------------------
extern "C" void kernel_launch(void* const* d_in, const int* in_sizes, int n_in,
                              void* d_out, int out_size)
{
    const int*   raw    = (const int*)d_in[0];
    const int*   aidx   = (const int*)d_in[1];
    const int*   left   = (const int*)d_in[2];
    const float* emb    = (const float*)d_in[3];
    const float* w_ih_f = (const float*)d_in[4];
    const float* w_hh_f = (const float*)d_in[5];
    const float* b_ih_f = (const float*)d_in[6];
    const float* b_hh_f = (const float*)d_in[7];
    const float* w_ih_b = (const float*)d_in[8];
    const float* w_hh_b = (const float*)d_in[9];
    const float* b_ih_b = (const float*)d_in[10];
    const float* b_hh_b = (const float*)d_in[11];
    const float* att_w  = (const float*)d_in[12];
    const float* gw_ih  = (const float*)d_in[14];
    const float* gw_hh  = (const float*)d_in[15];
    const float* gb_ih  = (const float*)d_in[16];
    const float* gb_hh  = (const float*)d_in[17];
    const float* dw     = (const float*)d_in[18];
    const float* db     = (const float*)d_in[19];
    float* out = (float*)d_out;

    const int LSTM_SMEM = 205312;
    cudaFuncSetAttribute(lstm_hmma_kernel,
                         cudaFuncAttributeMaxDynamicSharedMemorySize, LSTM_SMEM);

    lengths_kernel<<<Bn, Sn>>>(raw, aidx, left);                              // 0
    sort_kernel<<<1, 256>>>();                                                // 1
    megaprep_kernel<<<MP_TR, 256>>>(raw, emb, w_ih_f, w_ih_b,
                                    b_ih_f, b_hh_f, b_ih_b, b_hh_b,
                                    w_hh_f, w_hh_b, gw_ih, gw_hh);            // 2
    gemm_hmma_kernel<<<dim3(NPs/128, (Bn*Sn)/128), 256>>>();                  // 3
    lstm_hmma_kernel<<<120, LT, LSTM_SMEM>>>();                               // 4

    att_kernel<<<Bn, 256>>>(att_w);
    gi_kernel<<<64, 320>>>(gb_ih);
    for (int hop = 0; hop < 3; hop++)
        hop_kernel<<<64, 320>>>(gb_hh);
    dense_kernel<<<Bn, 96>>>(dw, db, out);
}